// round 3
// baseline (speedup 1.0000x reference)
#include <cuda_runtime.h>
#include <cuda_fp16.h>
#include <cstdint>

// Problem constants
#define M_TOK   4096
#define K_IN    3072
#define N_OUT   9216
#define GROUP   64
#define RANK    32
#define KE      3136          // 3072 + 32 (lora) + 32 (zero pad) -> multiple of 64
#define HEAD_DIM 128
#define N_HEADS 24

// ---------------- scratch (device globals: allocation-free) ----------------
__device__ __half g_A[(size_t)M_TOK * KE];   // dequantized activations + lora_act, fp16
__device__ __half g_W[(size_t)N_OUT * KE];   // dequantized weights + lora_up, fp16
__device__ int    g_qw_is_i32;               // 1 if qweight arrived as int32

// ---------------- detect qweight storage dtype ----------------
// If the harness stored int8 data as int32, every word is a sign-extended
// int8: (w >> 8) is 0 or -1. For packed int8 bytes the chance a random word
// passes is ~2^-23, so 8192 consecutive words all passing => int32.
__global__ void detect_qw_kernel(const int* __restrict__ qw32) {
    int ok = 1;
    for (int i = threadIdx.x; i < 8192; i += 256) {
        int hi = qw32[i] >> 8;
        if (hi != 0 && hi != -1) ok = 0;
    }
    __syncthreads();
    unsigned all = __all_sync(0xffffffffu, ok);
    __shared__ int wall[8];
    if ((threadIdx.x & 31) == 0) wall[threadIdx.x >> 5] = (int)all;
    __syncthreads();
    if (threadIdx.x == 0) {
        int r = 1;
        #pragma unroll
        for (int i = 0; i < 8; i++) r &= wall[i];
        g_qw_is_i32 = r;
    }
}

// ---------------- K0: weight dequant ----------------
__global__ void dequant_w_kernel(const void* __restrict__ qw_raw,
                                 const float* __restrict__ wsc) {
    int idx = blockIdx.x * 256 + threadIdx.x;
    const int TOT = N_OUT * (K_IN / 2);
    if (idx >= TOT) return;
    int n  = idx / (K_IN / 2);
    int jp = idx - n * (K_IN / 2);
    int k  = jp * 2;
    float s = wsc[(k >> 6) * N_OUT + n];
    int b;
    if (g_qw_is_i32) b = ((const int*)qw_raw)[idx];
    else             b = ((const int8_t*)qw_raw)[idx];
    int lo = ((b & 0xF) ^ 8) - 8;       // sign-extend low nibble
    int hi = (b << 24) >> 28;           // sign-extend high nibble of low byte
    __half2 hv = __floats2half2_rn((float)lo * s, (float)hi * s);
    *reinterpret_cast<__half2*>(&g_W[(size_t)n * KE + k]) = hv;
}

// append lora_up (cols 3072..3103) + zero pad (3104..3135)
__global__ void lora_w_kernel(const float* __restrict__ lup) {
    int n = blockIdx.x;
    int t = threadIdx.x;   // 0..63
    float v = (t < RANK) ? lup[n * RANK + t] : 0.0f;
    g_W[(size_t)n * KE + K_IN + t] = __float2half(v);
}

// ---------------- K1: activation quant + lora_act ----------------
__global__ void quant_act_kernel(const float* __restrict__ x,
                                 const float* __restrict__ smooth,
                                 const float* __restrict__ ldn) {
    __shared__ float xs[K_IN];
    __shared__ float part[8][RANK];
    int m    = blockIdx.x;
    int tid  = threadIdx.x;
    int lane = tid & 31;
    int w    = tid >> 5;

    const float* xr = x + (size_t)m * K_IN;
    for (int i = tid; i < K_IN; i += 256)
        xs[i] = __fdiv_rn(xr[i], smooth[i]);     // IEEE div, matches reference
    __syncthreads();

    // group quantization: 8 warps x 6 groups, 64 elems/group (2 per lane)
    #pragma unroll
    for (int j = 0; j < 6; j++) {
        int g  = w + 8 * j;
        int k1 = g * GROUP + lane;
        float v1 = xs[k1], v2 = xs[k1 + 32];
        float amax = fmaxf(fabsf(v1), fabsf(v2));
        #pragma unroll
        for (int o = 16; o > 0; o >>= 1)
            amax = fmaxf(amax, __shfl_xor_sync(0xffffffffu, amax, o));
        float ascale = fmaxf(__fdiv_rn(amax, 7.0f), 1e-8f);
        float q1 = fminf(fmaxf(rintf(__fdiv_rn(v1, ascale)), -8.0f), 7.0f);
        float q2 = fminf(fmaxf(rintf(__fdiv_rn(v2, ascale)), -8.0f), 7.0f);
        g_A[(size_t)m * KE + k1]      = __float2half(q1 * ascale);
        g_A[(size_t)m * KE + k1 + 32] = __float2half(q2 * ascale);
    }

    // lora_act[m][r] = sum_k xs[k] * lora_down[k][r]
    float acc = 0.0f;
    int kbeg = w * (K_IN / 8), kend = kbeg + (K_IN / 8);
    for (int k = kbeg; k < kend; k++)
        acc = fmaf(xs[k], ldn[k * RANK + lane], acc);
    part[w][lane] = acc;
    __syncthreads();
    if (w == 0) {
        float s = 0.0f;
        #pragma unroll
        for (int i = 0; i < 8; i++) s += part[i][lane];
        g_A[(size_t)m * KE + K_IN + lane] = __float2half(s);
    } else if (w == 1) {
        g_A[(size_t)m * KE + K_IN + RANK + lane] = __float2half(0.0f);  // pad
    }
}

// ---------------- K2: fp16 GEMM (mma.sync m16n8k16), C = A @ W^T + bias ----------------
#define BM 128
#define BN 128
#define BK 32
#define BKP 40            // padded row stride (halves); 80B, conflict-free ldmatrix

__device__ __forceinline__ void cp_async16(uint32_t dst, const void* src) {
    asm volatile("cp.async.cg.shared.global [%0], [%1], 16;" :: "r"(dst), "l"(src));
}
__device__ __forceinline__ void ldmx4(uint32_t addr, uint32_t& r0, uint32_t& r1,
                                      uint32_t& r2, uint32_t& r3) {
    asm volatile("ldmatrix.sync.aligned.m8n8.x4.shared.b16 {%0,%1,%2,%3}, [%4];"
                 : "=r"(r0), "=r"(r1), "=r"(r2), "=r"(r3) : "r"(addr));
}
__device__ __forceinline__ void mma16816(float* c, uint32_t a0, uint32_t a1,
                                         uint32_t a2, uint32_t a3,
                                         uint32_t b0, uint32_t b1) {
    asm volatile("mma.sync.aligned.m16n8k16.row.col.f32.f16.f16.f32 "
                 "{%0,%1,%2,%3}, {%4,%5,%6,%7}, {%8,%9}, {%0,%1,%2,%3};"
                 : "+f"(c[0]), "+f"(c[1]), "+f"(c[2]), "+f"(c[3])
                 : "r"(a0), "r"(a1), "r"(a2), "r"(a3), "r"(b0), "r"(b1));
}

__global__ void __launch_bounds__(256)
gemm_kernel(float* __restrict__ out, const float* __restrict__ bias) {
    __shared__ alignas(16) __half sA[2][BM][BKP];
    __shared__ alignas(16) __half sB[2][BN][BKP];

    const int tid  = threadIdx.x;
    const int lane = tid & 31;
    const int w    = tid >> 5;
    const int wm   = (w >> 2) * 64;    // warp m offset (2 warps in m)
    const int wn   = (w & 3) * 32;     // warp n offset (4 warps in n)
    const int bn   = blockIdx.x;       // 0..71
    const int bm   = blockIdx.y;       // 0..31
    const int m0   = bm * BM;
    const int n0   = bn * BN;

    const uint32_t sA_base = (uint32_t)__cvta_generic_to_shared(&sA[0][0][0]);
    const uint32_t sB_base = (uint32_t)__cvta_generic_to_shared(&sB[0][0][0]);

    auto load_stage = [&](int st, int kk) {
        #pragma unroll
        for (int i = 0; i < 2; i++) {
            int c   = tid + i * 256;          // 512 chunks of 16B per tile
            int row = c >> 2;
            int col = (c & 3) << 3;           // halves
            uint32_t da = sA_base + (((st * BM + row) * BKP + col) << 1);
            uint32_t db = sB_base + (((st * BN + row) * BKP + col) << 1);
            cp_async16(da, &g_A[(size_t)(m0 + row) * KE + kk + col]);
            cp_async16(db, &g_W[(size_t)(n0 + row) * KE + kk + col]);
        }
        asm volatile("cp.async.commit_group;");
    };

    float acc[4][4][4];
    #pragma unroll
    for (int mi = 0; mi < 4; mi++)
        #pragma unroll
        for (int ni = 0; ni < 4; ni++)
            #pragma unroll
            for (int q = 0; q < 4; q++) acc[mi][ni][q] = 0.0f;

    const int KT = KE / BK;  // 98
    load_stage(0, 0);

    for (int kt = 0; kt < KT; kt++) {
        if (kt + 1 < KT) {
            load_stage((kt + 1) & 1, (kt + 1) * BK);
            asm volatile("cp.async.wait_group 1;");
        } else {
            asm volatile("cp.async.wait_group 0;");
        }
        __syncthreads();

        const int st = kt & 1;
        #pragma unroll
        for (int ks = 0; ks < 2; ks++) {
            const int kq = ks * 16;
            uint32_t a[4][4];
            #pragma unroll
            for (int mi = 0; mi < 4; mi++) {
                int row = wm + mi * 16 + (lane & 15);
                int col = kq + ((lane >> 4) << 3);
                ldmx4(sA_base + (((st * BM + row) * BKP + col) << 1),
                      a[mi][0], a[mi][1], a[mi][2], a[mi][3]);
            }
            uint32_t b[2][4];
            #pragma unroll
            for (int nj = 0; nj < 2; nj++) {
                int row = wn + nj * 16 + (lane & 7) + ((lane >> 4) << 3);
                int col = kq + (((lane >> 3) & 1) << 3);
                ldmx4(sB_base + (((st * BN + row) * BKP + col) << 1),
                      b[nj][0], b[nj][1], b[nj][2], b[nj][3]);
            }
            #pragma unroll
            for (int mi = 0; mi < 4; mi++)
                #pragma unroll
                for (int ni = 0; ni < 4; ni++)
                    mma16816(acc[mi][ni],
                             a[mi][0], a[mi][1], a[mi][2], a[mi][3],
                             b[ni >> 1][(ni & 1) * 2 + 0],
                             b[ni >> 1][(ni & 1) * 2 + 1]);
        }
        __syncthreads();
    }

    // epilogue: + bias, fp32 stores
    #pragma unroll
    for (int ni = 0; ni < 4; ni++) {
        int gn = n0 + wn + ni * 8 + ((lane & 3) << 1);
        float b0 = __ldg(&bias[gn]);
        float b1 = __ldg(&bias[gn + 1]);
        #pragma unroll
        for (int mi = 0; mi < 4; mi++) {
            int gm = m0 + wm + mi * 16 + (lane >> 2);
            float2 v0 = make_float2(acc[mi][ni][0] + b0, acc[mi][ni][1] + b1);
            float2 v1 = make_float2(acc[mi][ni][2] + b0, acc[mi][ni][3] + b1);
            *reinterpret_cast<float2*>(&out[(size_t)gm * N_OUT + gn]) = v0;
            *reinterpret_cast<float2*>(&out[(size_t)(gm + 8) * N_OUT + gn]) = v1;
        }
    }
}

// ---------------- K3: RMSNorm + RoPE on Q and K sections, in place ----------------
__global__ void norm_rope_kernel(float* __restrict__ out,
                                 const float* __restrict__ nq,
                                 const float* __restrict__ nk,
                                 const float* __restrict__ rot) {
    int m   = blockIdx.x;
    int h   = blockIdx.y;            // 0..47 : 0-23 = q heads, 24-47 = k heads
    int sec = (h >= N_HEADS) ? 1 : 0;
    int head = h - sec * N_HEADS;
    int d   = threadIdx.x;           // 0..127
    size_t base = (size_t)m * N_OUT + (size_t)sec * (N_HEADS * HEAD_DIM)
                + (size_t)head * HEAD_DIM;

    float t  = out[base + d];
    float ss = t * t;
    #pragma unroll
    for (int o = 16; o > 0; o >>= 1) ss += __shfl_xor_sync(0xffffffffu, ss, o);

    __shared__ float ws[4];
    __shared__ float sm[HEAD_DIM];
    if ((d & 31) == 0) ws[d >> 5] = ss;
    __syncthreads();
    float tot = ws[0] + ws[1] + ws[2] + ws[3];
    float rn  = rsqrtf(tot * (1.0f / 128.0f) + 1e-6f);
    float g   = sec ? nk[d] : nq[d];
    sm[d] = t * rn * g;
    __syncthreads();

    if (d < 64) {
        float e = sm[2 * d], o2 = sm[2 * d + 1];
        float c = rot[(size_t)m * 128 + 2 * d];
        float s = rot[(size_t)m * 128 + 2 * d + 1];
        out[base + 2 * d]     = e * c - o2 * s;
        out[base + 2 * d + 1] = e * s + o2 * c;
    }
}

// ---------------- launch ----------------
extern "C" void kernel_launch(void* const* d_in, const int* in_sizes, int n_in,
                              void* d_out, int out_size) {
    const float*  x      = (const float*)d_in[0];
    const void*   qw     = d_in[1];                 // int8 OR int32 (detected)
    const float*  wsc    = (const float*)d_in[2];
    const float*  bias   = (const float*)d_in[3];
    const float*  ldn    = (const float*)d_in[4];
    const float*  lup    = (const float*)d_in[5];
    const float*  smooth = (const float*)d_in[6];
    const float*  nq     = (const float*)d_in[7];
    const float*  nk     = (const float*)d_in[8];
    const float*  rot    = (const float*)d_in[9];
    float* out = (float*)d_out;

    // Detect qweight on-wire dtype (int8 vs int32-promoted)
    detect_qw_kernel<<<1, 256>>>((const int*)qw);

    // K0: weight dequant (fp16) + lora_up append
    {
        int tot = N_OUT * (K_IN / 2);
        dequant_w_kernel<<<(tot + 255) / 256, 256>>>(qw, wsc);
        lora_w_kernel<<<N_OUT, 64>>>(lup);
    }
    // K1: activation quant (fp16) + lora_act append
    quant_act_kernel<<<M_TOK, 256>>>(x, smooth, ldn);
    // K2: GEMM + bias
    {
        dim3 grid(N_OUT / BN, M_TOK / BM);
        gemm_kernel<<<grid, 256>>>(out, bias);
    }
    // K3: norm + rope on q,k
    {
        dim3 grid(M_TOK, 2 * N_HEADS);
        norm_rope_kernel<<<grid, 128>>>(out, nq, nk, rot);
    }
}

// round 7
// speedup vs baseline: 1.0300x; 1.0300x over previous
#include <cuda_runtime.h>
#include <cuda_fp16.h>
#include <cstdint>

// Problem constants
#define M_TOK   4096
#define K_IN    3072
#define N_OUT   9216
#define GROUP   64
#define RANK    32
#define KE      3136          // 3072 + 32 (lora) + 32 (zero pad)
#define HEAD_DIM 128
#define N_HEADS 24

// ---------------- scratch (device globals: allocation-free) ----------------
__device__ __half g_A[(size_t)M_TOK * KE];   // dequantized activations + lora_act
__device__ __half g_W[(size_t)N_OUT * KE];   // dequantized weights + lora_up
__device__ int    g_qw_is_i32;

// ---------------- detect qweight storage dtype ----------------
__global__ void detect_qw_kernel(const int* __restrict__ qw32) {
    int ok = 1;
    for (int i = threadIdx.x; i < 8192; i += 256) {
        int hi = qw32[i] >> 8;
        if (hi != 0 && hi != -1) ok = 0;
    }
    __syncthreads();
    unsigned all = __all_sync(0xffffffffu, ok);
    __shared__ int wall[8];
    if ((threadIdx.x & 31) == 0) wall[threadIdx.x >> 5] = (int)all;
    __syncthreads();
    if (threadIdx.x == 0) {
        int r = 1;
        #pragma unroll
        for (int i = 0; i < 8; i++) r &= wall[i];
        g_qw_is_i32 = r;
    }
}

// ---------------- K0: weight dequant ----------------
__global__ void dequant_w_kernel(const void* __restrict__ qw_raw,
                                 const float* __restrict__ wsc) {
    int idx = blockIdx.x * 256 + threadIdx.x;
    const int TOT = N_OUT * (K_IN / 2);
    if (idx >= TOT) return;
    int n  = idx / (K_IN / 2);
    int jp = idx - n * (K_IN / 2);
    int k  = jp * 2;
    float s = wsc[(k >> 6) * N_OUT + n];
    int b;
    if (g_qw_is_i32) b = ((const int*)qw_raw)[idx];
    else             b = ((const int8_t*)qw_raw)[idx];
    int lo = ((b & 0xF) ^ 8) - 8;
    int hi = (b << 24) >> 28;
    __half2 hv = __floats2half2_rn((float)lo * s, (float)hi * s);
    *reinterpret_cast<__half2*>(&g_W[(size_t)n * KE + k]) = hv;
}

__global__ void lora_w_kernel(const float* __restrict__ lup) {
    int n = blockIdx.x;
    int t = threadIdx.x;   // 0..63
    float v = (t < RANK) ? lup[n * RANK + t] : 0.0f;
    g_W[(size_t)n * KE + K_IN + t] = __float2half(v);
}

// ---------------- K1: activation quant + lora_act ----------------
__global__ void quant_act_kernel(const float* __restrict__ x,
                                 const float* __restrict__ smooth,
                                 const float* __restrict__ ldn) {
    __shared__ float xs[K_IN];
    __shared__ float part[8][RANK];
    int m    = blockIdx.x;
    int tid  = threadIdx.x;
    int lane = tid & 31;
    int w    = tid >> 5;

    const float* xr = x + (size_t)m * K_IN;
    for (int i = tid; i < K_IN; i += 256)
        xs[i] = __fdiv_rn(xr[i], smooth[i]);
    __syncthreads();

    #pragma unroll
    for (int j = 0; j < 6; j++) {
        int g  = w + 8 * j;
        int k1 = g * GROUP + lane;
        float v1 = xs[k1], v2 = xs[k1 + 32];
        float amax = fmaxf(fabsf(v1), fabsf(v2));
        #pragma unroll
        for (int o = 16; o > 0; o >>= 1)
            amax = fmaxf(amax, __shfl_xor_sync(0xffffffffu, amax, o));
        float ascale = fmaxf(__fdiv_rn(amax, 7.0f), 1e-8f);
        float q1 = fminf(fmaxf(rintf(__fdiv_rn(v1, ascale)), -8.0f), 7.0f);
        float q2 = fminf(fmaxf(rintf(__fdiv_rn(v2, ascale)), -8.0f), 7.0f);
        g_A[(size_t)m * KE + k1]      = __float2half(q1 * ascale);
        g_A[(size_t)m * KE + k1 + 32] = __float2half(q2 * ascale);
    }

    float acc = 0.0f;
    int kbeg = w * (K_IN / 8), kend = kbeg + (K_IN / 8);
    for (int k = kbeg; k < kend; k++)
        acc = fmaf(xs[k], ldn[k * RANK + lane], acc);
    part[w][lane] = acc;
    __syncthreads();
    if (w == 0) {
        float s = 0.0f;
        #pragma unroll
        for (int i = 0; i < 8; i++) s += part[i][lane];
        g_A[(size_t)m * KE + K_IN + lane] = __float2half(s);
    } else if (w == 1) {
        g_A[(size_t)m * KE + K_IN + RANK + lane] = __float2half(0.0f);
    }
}

// ---------------- K2: fp16 GEMM 128x256, 4-stage cp.async, mma.sync ----------------
#define BM 128
#define BN 256
#define BK 32
#define BKP 40            // padded row stride (halves)
#define NSTAGE 4
#define KT (KE / BK)      // 98
// per-stage smem layout: A[128][40] then B[256][40], halves
#define ST_A_OFF   0
#define ST_B_OFF   (BM * BKP * 2)                 // 10240 bytes
#define ST_STRIDE  ((BM + BN) * BKP * 2)          // 30720 bytes
#define SMEM_TOTAL (NSTAGE * ST_STRIDE)           // 122880 bytes

__device__ __forceinline__ void cp_async16(uint32_t dst, const void* src) {
    asm volatile("cp.async.cg.shared.global [%0], [%1], 16;" :: "r"(dst), "l"(src));
}
__device__ __forceinline__ void ldmx4(uint32_t addr, uint32_t& r0, uint32_t& r1,
                                      uint32_t& r2, uint32_t& r3) {
    asm volatile("ldmatrix.sync.aligned.m8n8.x4.shared.b16 {%0,%1,%2,%3}, [%4];"
                 : "=r"(r0), "=r"(r1), "=r"(r2), "=r"(r3) : "r"(addr));
}
__device__ __forceinline__ void mma16816(float* c, uint32_t a0, uint32_t a1,
                                         uint32_t a2, uint32_t a3,
                                         uint32_t b0, uint32_t b1) {
    asm volatile("mma.sync.aligned.m16n8k16.row.col.f32.f16.f16.f32 "
                 "{%0,%1,%2,%3}, {%4,%5,%6,%7}, {%8,%9}, {%0,%1,%2,%3};"
                 : "+f"(c[0]), "+f"(c[1]), "+f"(c[2]), "+f"(c[3])
                 : "r"(a0), "r"(a1), "r"(a2), "r"(a3), "r"(b0), "r"(b1));
}

__global__ void __launch_bounds__(256, 1)
gemm_kernel(float* __restrict__ out, const float* __restrict__ bias) {
    extern __shared__ char smem[];
    uint32_t sbase;
    asm("{ .reg .u64 t; cvta.to.shared.u64 t, %1; cvt.u32.u64 %0, t; }"
        : "=r"(sbase) : "l"(smem));

    const int tid  = threadIdx.x;
    const int lane = tid & 31;
    const int w    = tid >> 5;
    const int wm   = (w >> 2) * 64;    // 2 warps in m
    const int wn   = (w & 3) * 64;     // 4 warps in n, 64 cols each
    const int m0   = blockIdx.y * BM;
    const int n0   = blockIdx.x * BN;

    auto load_stage = [&](int s, int kb) {
        const int k0 = kb * BK;
        const uint32_t st = sbase + s * ST_STRIDE;
        #pragma unroll
        for (int i = 0; i < 6; i++) {
            int c = tid + i * 256;     // 1536 chunks of 16B
            if (c < 512) {             // A: 128 rows x 4 chunks
                int row = c >> 2, col = (c & 3) << 3;
                cp_async16(st + ST_A_OFF + ((row * BKP + col) << 1),
                           &g_A[(size_t)(m0 + row) * KE + k0 + col]);
            } else {                   // B: 256 rows x 4 chunks
                int cb = c - 512;
                int row = cb >> 2, col = (cb & 3) << 3;
                cp_async16(st + ST_B_OFF + ((row * BKP + col) << 1),
                           &g_W[(size_t)(n0 + row) * KE + k0 + col]);
            }
        }
        asm volatile("cp.async.commit_group;");
    };

    float acc[4][8][4];
    #pragma unroll
    for (int mi = 0; mi < 4; mi++)
        #pragma unroll
        for (int ni = 0; ni < 8; ni++)
            #pragma unroll
            for (int q = 0; q < 4; q++) acc[mi][ni][q] = 0.0f;

    // prologue: fill 3 stages
    load_stage(0, 0);
    load_stage(1, 1);
    load_stage(2, 2);

    for (int kt = 0; kt < KT; kt++) {
        asm volatile("cp.async.wait_group 2;");
        __syncthreads();

        // issue next load into stage (kt+3)%4 (consumed last iter; safe after sync).
        // past the end: wrap to kb=0 into a stage that is never consumed.
        int kb_next = kt + 3;
        load_stage((kt + 3) & 3, kb_next < KT ? kb_next : 0);

        const uint32_t st = sbase + (kt & 3) * ST_STRIDE;
        #pragma unroll
        for (int ks = 0; ks < 2; ks++) {
            const int kq = ks * 16;
            uint32_t a[4][4];
            #pragma unroll
            for (int mi = 0; mi < 4; mi++) {
                int row = wm + mi * 16 + (lane & 15);
                int col = kq + ((lane >> 4) << 3);
                ldmx4(st + ST_A_OFF + ((row * BKP + col) << 1),
                      a[mi][0], a[mi][1], a[mi][2], a[mi][3]);
            }
            uint32_t b[4][4];
            #pragma unroll
            for (int nj = 0; nj < 4; nj++) {
                int row = wn + nj * 16 + (lane & 7) + ((lane >> 4) << 3);
                int col = kq + (((lane >> 3) & 1) << 3);
                ldmx4(st + ST_B_OFF + ((row * BKP + col) << 1),
                      b[nj][0], b[nj][1], b[nj][2], b[nj][3]);
            }
            #pragma unroll
            for (int mi = 0; mi < 4; mi++)
                #pragma unroll
                for (int ni = 0; ni < 8; ni++)
                    mma16816(acc[mi][ni],
                             a[mi][0], a[mi][1], a[mi][2], a[mi][3],
                             b[ni >> 1][(ni & 1) * 2 + 0],
                             b[ni >> 1][(ni & 1) * 2 + 1]);
        }
        __syncthreads();
    }

    // epilogue: + bias, fp32 stores
    #pragma unroll
    for (int ni = 0; ni < 8; ni++) {
        int gn = n0 + wn + ni * 8 + ((lane & 3) << 1);
        float b0 = __ldg(&bias[gn]);
        float b1 = __ldg(&bias[gn + 1]);
        #pragma unroll
        for (int mi = 0; mi < 4; mi++) {
            int gm = m0 + wm + mi * 16 + (lane >> 2);
            float2 v0 = make_float2(acc[mi][ni][0] + b0, acc[mi][ni][1] + b1);
            float2 v1 = make_float2(acc[mi][ni][2] + b0, acc[mi][ni][3] + b1);
            *reinterpret_cast<float2*>(&out[(size_t)gm * N_OUT + gn]) = v0;
            *reinterpret_cast<float2*>(&out[(size_t)(gm + 8) * N_OUT + gn]) = v1;
        }
    }
}

// ---------------- K3: RMSNorm + RoPE on Q and K sections, in place ----------------
__global__ void norm_rope_kernel(float* __restrict__ out,
                                 const float* __restrict__ nq,
                                 const float* __restrict__ nk,
                                 const float* __restrict__ rot) {
    int m   = blockIdx.x;
    int h   = blockIdx.y;            // 0..47
    int sec = (h >= N_HEADS) ? 1 : 0;
    int head = h - sec * N_HEADS;
    int d   = threadIdx.x;           // 0..127
    size_t base = (size_t)m * N_OUT + (size_t)sec * (N_HEADS * HEAD_DIM)
                + (size_t)head * HEAD_DIM;

    float t  = out[base + d];
    float ss = t * t;
    #pragma unroll
    for (int o = 16; o > 0; o >>= 1) ss += __shfl_xor_sync(0xffffffffu, ss, o);

    __shared__ float ws[4];
    __shared__ float sm[HEAD_DIM];
    if ((d & 31) == 0) ws[d >> 5] = ss;
    __syncthreads();
    float tot = ws[0] + ws[1] + ws[2] + ws[3];
    float rn  = rsqrtf(tot * (1.0f / 128.0f) + 1e-6f);
    float g   = sec ? nk[d] : nq[d];
    sm[d] = t * rn * g;
    __syncthreads();

    if (d < 64) {
        float e = sm[2 * d], o2 = sm[2 * d + 1];
        float c = rot[(size_t)m * 128 + 2 * d];
        float s = rot[(size_t)m * 128 + 2 * d + 1];
        out[base + 2 * d]     = e * c - o2 * s;
        out[base + 2 * d + 1] = e * s + o2 * c;
    }
}

// ---------------- launch ----------------
extern "C" void kernel_launch(void* const* d_in, const int* in_sizes, int n_in,
                              void* d_out, int out_size) {
    const float*  x      = (const float*)d_in[0];
    const void*   qw     = d_in[1];
    const float*  wsc    = (const float*)d_in[2];
    const float*  bias   = (const float*)d_in[3];
    const float*  ldn    = (const float*)d_in[4];
    const float*  lup    = (const float*)d_in[5];
    const float*  smooth = (const float*)d_in[6];
    const float*  nq     = (const float*)d_in[7];
    const float*  nk     = (const float*)d_in[8];
    const float*  rot    = (const float*)d_in[9];
    float* out = (float*)d_out;

    detect_qw_kernel<<<1, 256>>>((const int*)qw);

    {
        int tot = N_OUT * (K_IN / 2);
        dequant_w_kernel<<<(tot + 255) / 256, 256>>>(qw, wsc);
        lora_w_kernel<<<N_OUT, 64>>>(lup);
    }
    quant_act_kernel<<<M_TOK, 256>>>(x, smooth, ldn);

    cudaFuncSetAttribute(gemm_kernel,
                         cudaFuncAttributeMaxDynamicSharedMemorySize, SMEM_TOTAL);
    {
        dim3 grid(N_OUT / BN, M_TOK / BM);   // (36, 32)
        gemm_kernel<<<grid, 256, SMEM_TOTAL>>>(out, bias);
    }
    {
        dim3 grid(M_TOK, 2 * N_HEADS);
        norm_rope_kernel<<<grid, 128>>>(out, nq, nk, rot);
    }
}